// round 6
// baseline (speedup 1.0000x reference)
#include <cuda_runtime.h>

#define D_MODEL 512
static constexpr float INT64_MAX_F = 9.2233720368547758e18f;

// Scratch (no dynamic allocation allowed)
#define MAX_ACTORS (1 << 20)
#define NBUCKETS   8192
__device__ int g_counts[NBUCKETS];
__device__ int g_perm[MAX_ACTORS];

// ---------------------------------------------------------------------------
// Fused lgamma + digamma for t in [1, ~9]. Shift by 4 (y = t+4 >= 5),
// asymptotic series; recurrence product t(t+1)(t+2)(t+3) = u(u+2), u=t^2+3t.
// ---------------------------------------------------------------------------
__device__ __forceinline__ void lgamma_digamma(float t, float& lg, float& dg) {
    const float u = t * (t + 3.0f);
    const float d = u * (u + 2.0f);
    const float y = t + 4.0f;
    const float ln_y  = logf(y);
    const float inv_y = __fdividef(1.0f, y);
    const float inv2  = inv_y * inv_y;
    const float inv_d = __fdividef(1.0f, d);
    const float r    = (2.0f * t + 3.0f) * (2.0f * u + 2.0f) * inv_d;
    const float ln_p = logf(d);

    lg = fmaf(y - 0.5f, ln_y, -y) + 0.918938533204672742f
       + inv_y * (0.0833333333333f - inv2 * (0.00277777777778f - inv2 * 0.000793650793651f))
       - ln_p;
    dg = ln_y - 0.5f * inv_y
       - inv2 * (0.0833333333333f - inv2 * (0.00833333333333f - inv2 * 0.00396825396825f))
       - r;
}

// ---------------------------------------------------------------------------
// Sort pipeline: zero -> histogram -> scan -> scatter
// ---------------------------------------------------------------------------
__global__ void zero_counts_kernel() {
    g_counts[blockIdx.x * blockDim.x + threadIdx.x] = 0;
}

__global__ void hist_kernel(const int* __restrict__ actors, int n, int shift) {
    const int i = blockIdx.x * blockDim.x + threadIdx.x;
    if (i < n) {
        const int b = __ldg(actors + i) >> shift;
        atomicAdd(&g_counts[b], 1);
    }
}

// Single-block exclusive prefix sum over NBUCKETS entries. 1024 threads,
// each owns NBUCKETS/1024 consecutive buckets.
__global__ void __launch_bounds__(1024)
scan_kernel() {
    __shared__ int sh[1024];
    const int tid = threadIdx.x;
    const int per = NBUCKETS / 1024;
    const int base = tid * per;

    int local[NBUCKETS / 1024];
    int sum = 0;
    #pragma unroll
    for (int k = 0; k < per; k++) {
        local[k] = sum;
        sum += g_counts[base + k];
    }
    sh[tid] = sum;
    __syncthreads();
    // Hillis–Steele inclusive scan of thread totals
    #pragma unroll
    for (int off = 1; off < 1024; off <<= 1) {
        int v = (tid >= off) ? sh[tid - off] : 0;
        __syncthreads();
        sh[tid] += v;
        __syncthreads();
    }
    const int offset = sh[tid] - sum;  // exclusive
    #pragma unroll
    for (int k = 0; k < per; k++)
        g_counts[base + k] = offset + local[k];
}

__global__ void scatter_kernel(const int* __restrict__ actors, int n, int shift) {
    const int i = blockIdx.x * blockDim.x + threadIdx.x;
    if (i < n) {
        const int b = __ldg(actors + i) >> shift;
        const int pos = atomicAdd(&g_counts[b], 1);
        g_perm[pos] = i;
    }
}

// ---------------------------------------------------------------------------
// Kernel A: gather + dual dot product, visiting actors in bucket-sorted order.
// One warp handles 4 permuted actors; results written to ORIGINAL positions.
// ---------------------------------------------------------------------------
__global__ void __launch_bounds__(256)
cah_gemv_kernel(const float* __restrict__ x,
                const int*   __restrict__ actors,
                const float* __restrict__ w,
                const float* __restrict__ bvec,
                float*       __restrict__ out,
                int n_actors)
{
    const int lane = threadIdx.x & 31;
    const int warp = (blockIdx.x * blockDim.x + threadIdx.x) >> 5;

    const int j0 = warp * 4;
    if (j0 >= n_actors) return;

    // Preload w into registers: lane covers columns j*128 + lane*4
    float4 w0r[4], w1r[4];
    #pragma unroll
    for (int j = 0; j < 4; j++) {
        int c = j * 128 + lane * 4;
        w0r[j] = *reinterpret_cast<const float4*>(w + c);
        w1r[j] = *reinterpret_cast<const float4*>(w + D_MODEL + c);
    }
    const float b0 = bvec[0];
    const float b1 = bvec[1];

    int idx[4];
    const float4* xr[4];
    #pragma unroll
    for (int q = 0; q < 4; q++) {
        const int j = (j0 + q < n_actors) ? (j0 + q) : j0;
        idx[q] = __ldg(&g_perm[j]);
        const int row = __ldg(actors + idx[q]);
        xr[q] = reinterpret_cast<const float4*>(x + (size_t)row * D_MODEL);
    }

    // 16 independent 16B gathers per lane, all issued before any use
    float4 v[4][4];
    #pragma unroll
    for (int q = 0; q < 4; q++)
        #pragma unroll
        for (int j = 0; j < 4; j++)
            v[q][j] = __ldg(xr[q] + j * 32 + lane);

    float acc[4][2];
    #pragma unroll
    for (int q = 0; q < 4; q++) {
        float s0 = 0.0f, s1 = 0.0f;
        #pragma unroll
        for (int j = 0; j < 4; j++) {
            s0 = fmaf(v[q][j].x, w0r[j].x, s0); s0 = fmaf(v[q][j].y, w0r[j].y, s0);
            s0 = fmaf(v[q][j].z, w0r[j].z, s0); s0 = fmaf(v[q][j].w, w0r[j].w, s0);
            s1 = fmaf(v[q][j].x, w1r[j].x, s1); s1 = fmaf(v[q][j].y, w1r[j].y, s1);
            s1 = fmaf(v[q][j].z, w1r[j].z, s1); s1 = fmaf(v[q][j].w, w1r[j].w, s1);
        }
        acc[q][0] = s0; acc[q][1] = s1;
    }

    #pragma unroll
    for (int off = 16; off > 0; off >>= 1) {
        #pragma unroll
        for (int q = 0; q < 4; q++) {
            acc[q][0] += __shfl_xor_sync(0xffffffffu, acc[q][0], off);
            acc[q][1] += __shfl_xor_sync(0xffffffffu, acc[q][1], off);
        }
    }

    if (lane == 0) {
        #pragma unroll
        for (int q = 0; q < 4; q++) {
            if (j0 + q < n_actors) {
                const float z0 = acc[q][0] + b0;
                const float z1 = acc[q][1] + b1;
                float2 l;
                l.x = fmaf(z0, z0, 1.0f);
                l.y = fmaf(z1, z1, 1.0f);
                *reinterpret_cast<float2*>(out + 3 * (size_t)n_actors + 2 * (size_t)idx[q]) = l;
            }
        }
    }
}

// ---------------------------------------------------------------------------
// Kernel B: fully parallel epilogue. One thread per actor.
// ---------------------------------------------------------------------------
__global__ void __launch_bounds__(256)
cah_epilogue_kernel(const int* __restrict__ prev,
                    float*     __restrict__ out,
                    int n_actors)
{
    const int i = blockIdx.x * blockDim.x + threadIdx.x;
    if (i >= n_actors) return;

    const float2 l = *reinterpret_cast<const float2*>(out + 3 * (size_t)n_actors + 2 * (size_t)i);
    const float a  = l.x;
    const float bb = l.y;

    const float pa     = (float)__ldg(prev + i);
    const float action = pa * (1.0f / INT64_MAX_F);

    float lga, dga, lgb, dgb, lgab, dgab;
    lgamma_digamma(a,      lga,  dga);
    lgamma_digamma(bb,     lgb,  dgb);
    lgamma_digamma(a + bb, lgab, dgab);

    const float lbeta = lga + lgb - lgab;

    const float logprob = (a - 1.0f) * logf(action)
                        + (bb - 1.0f) * log1pf(-action)
                        - lbeta;

    const float ent = lbeta
                    - (a - 1.0f)  * dga
                    - (bb - 1.0f) * dgb
                    + (a + bb - 2.0f) * dgab;

    out[i]                        = action * INT64_MAX_F;
    out[(size_t)n_actors + i]     = logprob;
    out[2 * (size_t)n_actors + i] = ent;
}

extern "C" void kernel_launch(void* const* d_in, const int* in_sizes, int n_in,
                              void* d_out, int out_size)
{
    const float* x      = (const float*)d_in[0];
    const int*   actors = (const int*)  d_in[1];
    const float* w      = (const float*)d_in[2];
    const float* bvec   = (const float*)d_in[3];
    const int*   prev   = (const int*)  d_in[4];
    float*       out    = (float*)d_out;

    const int n_actors     = in_sizes[1];
    const int total_tokens = in_sizes[0] / D_MODEL;

    // shift so that (total_tokens >> shift) <= NBUCKETS
    int shift = 0;
    while ((total_tokens >> shift) > NBUCKETS) shift++;

    const int T = 256;
    const int nb_blocks = (n_actors + T - 1) / T;

    zero_counts_kernel<<<NBUCKETS / T, T>>>();
    hist_kernel<<<nb_blocks, T>>>(actors, n_actors, shift);
    scan_kernel<<<1, 1024>>>();
    scatter_kernel<<<nb_blocks, T>>>(actors, n_actors, shift);

    const int warpsA  = (n_actors + 3) / 4;
    const int blocksA = (warpsA * 32 + T - 1) / T;
    cah_gemv_kernel<<<blocksA, T>>>(x, actors, w, bvec, out, n_actors);

    const int blocksB = (n_actors + T - 1) / T;
    cah_epilogue_kernel<<<blocksB, T>>>(prev, out, n_actors);
}

// round 7
// speedup vs baseline: 1.2208x; 1.2208x over previous
#include <cuda_runtime.h>

#define D_MODEL 512
static constexpr float INT64_MAX_F = 9.2233720368547758e18f;

// ---------------------------------------------------------------------------
// Fused lgamma + digamma for t in [1, ~9]. Shift by 4 (y = t+4 >= 5),
// asymptotic series; recurrence product t(t+1)(t+2)(t+3) = u(u+2), u=t^2+3t.
// ---------------------------------------------------------------------------
__device__ __forceinline__ void lgamma_digamma(float t, float& lg, float& dg) {
    const float u = t * (t + 3.0f);
    const float d = u * (u + 2.0f);
    const float y = t + 4.0f;
    const float ln_y  = logf(y);
    const float inv_y = __fdividef(1.0f, y);
    const float inv2  = inv_y * inv_y;
    const float inv_d = __fdividef(1.0f, d);
    const float r    = (2.0f * t + 3.0f) * (2.0f * u + 2.0f) * inv_d;
    const float ln_p = logf(d);

    lg = fmaf(y - 0.5f, ln_y, -y) + 0.918938533204672742f
       + inv_y * (0.0833333333333f - inv2 * (0.00277777777778f - inv2 * 0.000793650793651f))
       - ln_p;
    dg = ln_y - 0.5f * inv_y
       - inv2 * (0.0833333333333f - inv2 * (0.00833333333333f - inv2 * 0.00396825396825f))
       - r;
}

// ---------------------------------------------------------------------------
// Fully fused kernel: one warp handles 4 actors.
//   - gather 4 rows (16 independent float4 loads per lane, coalesced)
//   - dual dot products + butterfly reduction (all lanes hold all 8 sums)
//   - lanes 0..3 each run the complete scalar epilogue for one actor,
//     hidden under the warp's memory-throughput-bound gather time.
// ---------------------------------------------------------------------------
__global__ void __launch_bounds__(256)
cah_fused_kernel(const float* __restrict__ x,
                 const int*   __restrict__ actors,
                 const float* __restrict__ w,
                 const float* __restrict__ bvec,
                 const int*   __restrict__ prev,
                 float*       __restrict__ out,
                 int n_actors)
{
    const int lane = threadIdx.x & 31;
    const int warp = (blockIdx.x * blockDim.x + threadIdx.x) >> 5;

    const int i0 = warp * 4;
    if (i0 >= n_actors) return;

    // Preload w into registers: lane covers columns j*128 + lane*4
    float4 w0r[4], w1r[4];
    #pragma unroll
    for (int j = 0; j < 4; j++) {
        int c = j * 128 + lane * 4;
        w0r[j] = *reinterpret_cast<const float4*>(w + c);
        w1r[j] = *reinterpret_cast<const float4*>(w + D_MODEL + c);
    }
    const float b0 = bvec[0];
    const float b1 = bvec[1];

    // Prefetch this lane's prev value early (lanes 0..3 use it at the end)
    const int my_i   = i0 + lane;
    const bool do_ep = (lane < 4) && (my_i < n_actors);
    float pa = 0.0f;
    if (do_ep) pa = (float)__ldg(prev + my_i);

    // Row pointers
    const float4* xr[4];
    #pragma unroll
    for (int q = 0; q < 4; q++) {
        const int idx = (i0 + q < n_actors) ? (i0 + q) : i0;
        const int row = __ldg(actors + idx);
        xr[q] = reinterpret_cast<const float4*>(x + (size_t)row * D_MODEL);
    }

    // 16 independent 16B gathers per lane, all issued before any use
    float4 v[4][4];
    #pragma unroll
    for (int q = 0; q < 4; q++)
        #pragma unroll
        for (int j = 0; j < 4; j++)
            v[q][j] = __ldg(xr[q] + j * 32 + lane);

    float acc[4][2];
    #pragma unroll
    for (int q = 0; q < 4; q++) {
        float s0 = 0.0f, s1 = 0.0f;
        #pragma unroll
        for (int j = 0; j < 4; j++) {
            s0 = fmaf(v[q][j].x, w0r[j].x, s0); s0 = fmaf(v[q][j].y, w0r[j].y, s0);
            s0 = fmaf(v[q][j].z, w0r[j].z, s0); s0 = fmaf(v[q][j].w, w0r[j].w, s0);
            s1 = fmaf(v[q][j].x, w1r[j].x, s1); s1 = fmaf(v[q][j].y, w1r[j].y, s1);
            s1 = fmaf(v[q][j].z, w1r[j].z, s1); s1 = fmaf(v[q][j].w, w1r[j].w, s1);
        }
        acc[q][0] = s0; acc[q][1] = s1;
    }

    // Butterfly reduction: afterwards EVERY lane holds all 8 full sums
    #pragma unroll
    for (int off = 16; off > 0; off >>= 1) {
        #pragma unroll
        for (int q = 0; q < 4; q++) {
            acc[q][0] += __shfl_xor_sync(0xffffffffu, acc[q][0], off);
            acc[q][1] += __shfl_xor_sync(0xffffffffu, acc[q][1], off);
        }
    }

    // Lanes 0..3: full epilogue for actor i0+lane
    if (do_ep) {
        const float z0 = acc[lane][0] + b0;
        const float z1 = acc[lane][1] + b1;
        const float a  = fmaf(z0, z0, 1.0f);
        const float bb = fmaf(z1, z1, 1.0f);

        const float action = pa * (1.0f / INT64_MAX_F);

        float lga, dga, lgb, dgb, lgab, dgab;
        lgamma_digamma(a,      lga,  dga);
        lgamma_digamma(bb,     lgb,  dgb);
        lgamma_digamma(a + bb, lgab, dgab);

        const float lbeta = lga + lgb - lgab;

        const float logprob = (a - 1.0f) * logf(action)
                            + (bb - 1.0f) * log1pf(-action)
                            - lbeta;

        const float ent = lbeta
                        - (a - 1.0f)  * dga
                        - (bb - 1.0f) * dgb
                        + (a + bb - 2.0f) * dgab;

        out[my_i]                        = action * INT64_MAX_F;
        out[(size_t)n_actors + my_i]     = logprob;
        out[2 * (size_t)n_actors + my_i] = ent;
        float2 l; l.x = a; l.y = bb;
        *reinterpret_cast<float2*>(out + 3 * (size_t)n_actors + 2 * (size_t)my_i) = l;
    }
}

extern "C" void kernel_launch(void* const* d_in, const int* in_sizes, int n_in,
                              void* d_out, int out_size)
{
    const float* x      = (const float*)d_in[0];
    const int*   actors = (const int*)  d_in[1];
    const float* w      = (const float*)d_in[2];
    const float* bvec   = (const float*)d_in[3];
    const int*   prev   = (const int*)  d_in[4];
    float*       out    = (float*)d_out;

    const int n_actors = in_sizes[1];  // 262144

    const int T       = 256;
    const int warps   = (n_actors + 3) / 4;
    const int blocks  = (warps * 32 + T - 1) / T;
    cah_fused_kernel<<<blocks, T>>>(x, actors, w, bvec, prev, out, n_actors);
}